// round 9
// baseline (speedup 1.0000x reference)
#include <cuda_runtime.h>
#include <cstdint>

// out[r,k] = 2^-11 * (WHT_2048(concat(x1,x2))[r,k])^2
// RZ phase cancels under |.|^2; real input -> real state.
//
// Persistent CTAs (128 thr), cp.async double-buffered row pipeline:
//   cp.async.cg streams row k+1 into buf[(k+1)&1] while buf[k&1] is computed.
//   Padded smem layout a(i) = i[10:7]*136 + i[6]*68 + i[5:0] (64-float chunks
//   contiguous -> 16B cp.async friendly; all LDS/STS patterns conflict-free,
//   verified in R4/R5).
//   phase1 regs: bits 7..10 (in-place), phase2 regs: bits 2..5 (in-place),
//   phase3 regs: bits 0,1,6 -> coalesced STG.128.

#define CP_ASYNC_CG16(dst_u32, src_ptr) \
    asm volatile("cp.async.cg.shared.global [%0], [%1], 16;\n" \
                 :: "r"(dst_u32), "l"(src_ptr))
#define CP_COMMIT()  asm volatile("cp.async.commit_group;\n")
#define CP_WAIT_1()  asm volatile("cp.async.wait_group 1;\n" ::: "memory")

__global__ __launch_bounds__(128, 13)
void qfl_wht_kernel(const float* __restrict__ x1,
                    const float* __restrict__ x2,
                    float* __restrict__ out, int rows)
{
    __shared__ float smem[2][2176];            // 2 x 8704 B padded row buffers

    const int t = threadIdx.x;                 // 0..127

    // ---- cp.async loader: row -> padded buffer ----------------------------
    // 32 chunks of 64 floats: chunk c covers elements r*128 + i6*64 + [0,64),
    // r = c>>1, i6 = c&1; dst = r*136 + i6*68. Thread t copies 16B piece
    // j = (t&15)*4 of chunks {t>>4, t>>4+8, t>>4+16, t>>4+24}.
    const int c0 = t >> 4;
    const int jw = (t & 15) << 2;              // word offset within chunk

    auto load_row = [&](int bufsel, int row) {
        uint32_t sbase = (uint32_t)__cvta_generic_to_shared(smem[bufsel]);
#pragma unroll
        for (int h = 0; h < 4; ++h) {
            const int c  = c0 + (h << 3);      // 0..31
            const int r  = c >> 1;             // 0..15
            const int i6 = c & 1;
            uint32_t dst = sbase + (uint32_t)((r * 136 + i6 * 68 + jw) << 2);
            const float* src = (r < 8)
                ? (x1 + (size_t)row * 1024 + (r << 7)       + (i6 << 6) + jw)
                : (x2 + (size_t)row * 1024 + ((r - 8) << 7) + (i6 << 6) + jw);
            CP_ASYNC_CG16(dst, src);
        }
    };

    const int G  = gridDim.x;
    const int r0 = blockIdx.x;

    // ---- Prologue: prefetch depth 2 ---------------------------------------
    load_row(0, r0);
    CP_COMMIT();
    if (r0 + G < rows) load_row(1, r0 + G);
    CP_COMMIT();                                // (possibly empty group)

    int k = 0;
    for (int row = r0; row < rows; row += G, ++k) {
        CP_WAIT_1();                            // group k complete
        __syncthreads();                        // B0: buffer visible block-wide
        float* buf = smem[k & 1];

        // ---- Phase 1: i[6:0]=t, regs = bits 7..10; in-place ---------------
        const int wbase = ((t >> 6) * 68) + (t & 63);
        float v[16];
#pragma unroll
        for (int r = 0; r < 16; ++r) v[r] = buf[r * 136 + wbase];

#pragma unroll
        for (int m = 1; m <= 8; m <<= 1) {
#pragma unroll
            for (int r = 0; r < 16; ++r) {
                if (!(r & m)) {
                    float a = v[r], b = v[r | m];
                    v[r]     = a + b;
                    v[r | m] = a - b;
                }
            }
        }
#pragma unroll
        for (int r = 0; r < 16; ++r) buf[r * 136 + wbase] = v[r];
        __syncthreads();                        // B1

        // ---- Phase 2: regs own q = i[5:2]; in-place -----------------------
        const int base2 = (t >> 3) * 136 + ((t >> 2) & 1) * 68 + (t & 3);
#pragma unroll
        for (int q = 0; q < 16; ++q) v[q] = buf[base2 + (q << 2)];

#pragma unroll
        for (int m = 1; m <= 8; m <<= 1) {
#pragma unroll
            for (int q = 0; q < 16; ++q) {
                if (!(q & m)) {
                    float a = v[q], b = v[q | m];
                    v[q]     = a + b;
                    v[q | m] = a - b;
                }
            }
        }
#pragma unroll
        for (int q = 0; q < 16; ++q) buf[base2 + (q << 2)] = v[q];
        __syncthreads();                        // B2

        // ---- Phase 3: regs own i[1:0] (float4), i6 (d&1), i7 (d>>1) -------
        const int base3 = (t >> 4) * 272 + ((t & 15) << 2);
        float4 u[4];
#pragma unroll
        for (int d = 0; d < 4; ++d) {
            const int off = (d >> 1) * 136 + (d & 1) * 68;
            u[d] = *(const float4*)&buf[base3 + off];   // conflict-free LDS.128
        }
        __syncthreads();                        // B3: buffer free for refill

        // ---- Refill this buffer with row k+2 (overlaps tail compute) ------
        {
            const int nrow = row + 2 * G;
            if (nrow < rows) load_row(k & 1, nrow);
            CP_COMMIT();                        // (possibly empty group)
        }

        // butterflies on bits 0 and 1 (inside float4)
#pragma unroll
        for (int d = 0; d < 4; ++d) {
            float a0 = u[d].x, a1 = u[d].y, a2 = u[d].z, a3 = u[d].w;
            float s0 = a0 + a1, d0 = a0 - a1;
            float s2 = a2 + a3, d2v = a2 - a3;
            u[d].x = s0 + s2;  u[d].z = s0 - s2;
            u[d].y = d0 + d2v; u[d].w = d0 - d2v;
        }
        // butterfly on bit 6 (d&1): pairs (0,1) and (2,3)
#pragma unroll
        for (int dd = 0; dd < 4; dd += 2) {
            float4 a = u[dd], b = u[dd + 1];
            u[dd]     = make_float4(a.x + b.x, a.y + b.y, a.z + b.z, a.w + b.w);
            u[dd + 1] = make_float4(a.x - b.x, a.y - b.y, a.z - b.z, a.w - b.w);
        }

        // ---- Square, scale, coalesced streaming STG.128 -------------------
        const float sc = 1.0f / 2048.0f;
        float* o = out + (size_t)row * 2048 + (t >> 4) * 256 + ((t & 15) << 2);
#pragma unroll
        for (int d = 0; d < 4; ++d) {
            float4 w = u[d];
            w.x = w.x * w.x * sc;
            w.y = w.y * w.y * sc;
            w.z = w.z * w.z * sc;
            w.w = w.w * w.w * sc;
            __stcs((float4*)&o[(d >> 1) * 128 + (d & 1) * 64], w);
        }
    }
}

extern "C" void kernel_launch(void* const* d_in, const int* in_sizes, int n_in,
                              void* d_out, int out_size)
{
    const float* x1 = (const float*)d_in[0];   // (8192, 1024) f32
    const float* x2 = (const float*)d_in[1];   // (8192, 1024) f32
    float* out = (float*)d_out;                // (8192, 2048) f32

    const int rows = in_sizes[0] / 1024;       // 8192
    int grid = 152 * 13;                       // 13 CTAs/SM (smem-limited), persistent
    if (grid > rows) grid = rows;
    qfl_wht_kernel<<<grid, 128>>>(x1, x2, out, rows);
}

// round 10
// speedup vs baseline: 1.0795x; 1.0795x over previous
#include <cuda_runtime.h>

// out[r,k] = 2^-11 * (WHT_2048(concat(x1,x2))[r,k])^2
// RZ phase cancels under |.|^2; real input -> real state.
//
// One row per 128-thread block (16 blocks/SM, regs=32 -> full RF):
//   phase1 regs: bits 7..10  (i = r*128 + t, 16 coalesced scalar LDG)
//   phase2 regs: bits 2..5   (after transpose 1; in-place write-back)
//   phase3 regs: bits 0,1,6  (+bit7 passenger; LDS.128, coalesced STG.128)
// Padded smem layout a(i) = i[10:7]*136 + i[6]*68 + i[5:0] -> STS1, LDS1,
// STS2, LDS2.128 all bank-conflict-free (verified R4/R5).
//
// Cache policy (steady-state replay loop, 128MB working set vs 126MB L2):
//   input : __ldcs  (read-once -> stream, evict-first, frees L2 capacity)
//   output: default write-back stores (evict-normal) -> dirty lines stay in
//           L2 and are overwritten by the next replay, eliding DRAM writes.

__global__ __launch_bounds__(128, 16)
void qfl_wht_kernel(const float* __restrict__ x1,
                    const float* __restrict__ x2,
                    float* __restrict__ out)
{
    __shared__ float s[2176];            // 8704 B/row

    const int t   = threadIdx.x;         // 0..127
    const int row = blockIdx.x;

    // ---- Phase 1 load: i = r*128 + t (bits 7..10 in regs), coalesced ------
    float v[16];
    const float* p1 = x1 + (size_t)row * 1024 + t;
    const float* p2 = x2 + (size_t)row * 1024 + t;
#pragma unroll
    for (int r = 0; r < 8; ++r) v[r]     = __ldcs(p1 + (r << 7));
#pragma unroll
    for (int r = 0; r < 8; ++r) v[8 + r] = __ldcs(p2 + (r << 7));

    // butterflies on bits 7..10 (r index)
#pragma unroll
    for (int m = 1; m <= 8; m <<= 1) {
#pragma unroll
        for (int r = 0; r < 16; ++r) {
            if (!(r & m)) {
                float a = v[r], b = v[r | m];
                v[r]     = a + b;
                v[r | m] = a - b;
            }
        }
    }

    // ---- Transpose 1: a(i) = i[10:7]*136 + i[6]*68 + i[5:0]; i[6:0] = t ---
    {
        const int wbase = ((t >> 6) * 68) + (t & 63);
#pragma unroll
        for (int r = 0; r < 16; ++r) s[r * 136 + wbase] = v[r];
    }
    __syncthreads();

    // ---- Phase 2: regs own q = i[5:2]; thread: i[10:7]=t>>3, i6=t[2], i[1:0]=t[1:0]
    const int base2 = (t >> 3) * 136 + ((t >> 2) & 1) * 68 + (t & 3);
#pragma unroll
    for (int q = 0; q < 16; ++q) v[q] = s[base2 + (q << 2)];

    // butterflies on bits 2..5 (q index)
#pragma unroll
    for (int m = 1; m <= 8; m <<= 1) {
#pragma unroll
        for (int q = 0; q < 16; ++q) {
            if (!(q & m)) {
                float a = v[q], b = v[q | m];
                v[q]     = a + b;
                v[q | m] = a - b;
            }
        }
    }

    // in-place write-back (identical ownership partition -> race-free)
#pragma unroll
    for (int q = 0; q < 16; ++q) s[base2 + (q << 2)] = v[q];
    __syncthreads();

    // ---- Phase 3: regs own i[1:0] (float4), i6 (d&1), i7 passenger (d>>1) -
    const int base3 = (t >> 4) * 272 + ((t & 15) << 2);
    float4 u[4];
#pragma unroll
    for (int d = 0; d < 4; ++d) {
        const int off = (d >> 1) * 136 + (d & 1) * 68;
        u[d] = *(const float4*)&s[base3 + off];   // conflict-free LDS.128
    }

    // butterflies on bits 0 and 1 (inside float4)
#pragma unroll
    for (int d = 0; d < 4; ++d) {
        float a0 = u[d].x, a1 = u[d].y, a2 = u[d].z, a3 = u[d].w;
        float s0 = a0 + a1, d0 = a0 - a1;
        float s2 = a2 + a3, d2v = a2 - a3;
        u[d].x = s0 + s2;  u[d].z = s0 - s2;
        u[d].y = d0 + d2v; u[d].w = d0 - d2v;
    }
    // butterfly on bit 6 (d&1): pairs (0,1) and (2,3)
#pragma unroll
    for (int dd = 0; dd < 4; dd += 2) {
        float4 a = u[dd], b = u[dd + 1];
        u[dd]     = make_float4(a.x + b.x, a.y + b.y, a.z + b.z, a.w + b.w);
        u[dd + 1] = make_float4(a.x - b.x, a.y - b.y, a.z - b.z, a.w - b.w);
    }

    // ---- Square, scale, coalesced write-back STG.128 (keep lines in L2) ---
    const float sc = 1.0f / 2048.0f;
    float* o = out + (size_t)row * 2048 + (t >> 4) * 256 + ((t & 15) << 2);
#pragma unroll
    for (int d = 0; d < 4; ++d) {
        float4 w = u[d];
        w.x = w.x * w.x * sc;
        w.y = w.y * w.y * sc;
        w.z = w.z * w.z * sc;
        w.w = w.w * w.w * sc;
        *(float4*)&o[(d >> 1) * 128 + (d & 1) * 64] = w;   // default wb store
    }
}

extern "C" void kernel_launch(void* const* d_in, const int* in_sizes, int n_in,
                              void* d_out, int out_size)
{
    const float* x1 = (const float*)d_in[0];   // (8192, 1024) f32
    const float* x2 = (const float*)d_in[1];   // (8192, 1024) f32
    float* out = (float*)d_out;                // (8192, 2048) f32

    const int rows = in_sizes[0] / 1024;       // 8192
    qfl_wht_kernel<<<rows, 128>>>(x1, x2, out);
}

// round 12
// speedup vs baseline: 1.1875x; 1.1000x over previous
#include <cuda_runtime.h>

// out[r,k] = 2^-11 * (WHT_2048(concat(x1,x2))[r,k])^2
// RZ phase cancels under |.|^2; real input -> real state.
//
// One row per 128-thread block, 16 blocks/SM. MIRRORED phase assignment vs R5
// to cut front-batched-LDG count (MLP_p1 16 -> 4) and overlap loads w/ compute:
//   phase1 regs: bits 0,1,6 (+bit7 passenger) -- 4x LDG.128, butterflies start
//                per-float4 as data arrives, 4x STS.128
//   phase2 regs: bits 2..5   (scalar LDS/STS, in-place, conflict-free)
//   phase3 regs: bits 7..10  (16 conflict-free scalar LDS, 16 coalesced STG)
// Padded smem layout a(i) = i[10:7]*136 + i[6]*68 + i[5:0]; all access
// patterns bank-conflict-free (p2/p3 patterns verified in R4/R5; p1 STS.128
// cols per 8-lane phase = (t&15 + 68*(t>>4)) mod 8, distinct).

__global__ __launch_bounds__(128, 16)
void qfl_wht_kernel(const float* __restrict__ x1,
                    const float* __restrict__ x2,
                    float* __restrict__ out)
{
    __shared__ float s[2176];            // 8704 B/row

    const int t   = threadIdx.x;         // 0..127
    const int row = blockIdx.x;

    // ---- Phase 1: 4x LDG.128 -----------------------------------------------
    // Element i = (t>>4)*256 + (d>>1)*128 + (d&1)*64 + (t&15)*4 + j
    //   regs own: i[1:0]=j (float4), i6=d&1, i7=d>>1 (passenger)
    //   thread:   i[5:2]=t&15, i[10:8]=t>>4
    const float* srcb = ((t < 64) ? x1 : x2)
                      + (size_t)row * 1024 + ((t >> 4) & 3) * 256 + ((t & 15) << 2);
    float4 u[4];
#pragma unroll
    for (int d = 0; d < 4; ++d)
        u[d] = __ldcs((const float4*)(srcb + (d >> 1) * 128 + (d & 1) * 64));

    // butterflies on bits 0 and 1 (inside each float4; overlaps later loads)
#pragma unroll
    for (int d = 0; d < 4; ++d) {
        float a0 = u[d].x, a1 = u[d].y, a2 = u[d].z, a3 = u[d].w;
        float s0 = a0 + a1, d0 = a0 - a1;
        float s2 = a2 + a3, d2 = a2 - a3;
        u[d].x = s0 + s2;  u[d].z = s0 - s2;
        u[d].y = d0 + d2;  u[d].w = d0 - d2;
    }
    // butterfly on bit 6 (d&1): pairs (0,1) and (2,3); bit 7 (d>>1) passenger
#pragma unroll
    for (int dd = 0; dd < 4; dd += 2) {
        float4 a = u[dd], b = u[dd + 1];
        u[dd]     = make_float4(a.x + b.x, a.y + b.y, a.z + b.z, a.w + b.w);
        u[dd + 1] = make_float4(a.x - b.x, a.y - b.y, a.z - b.z, a.w - b.w);
    }

    // STS.128 into padded layout: i[10:7] = (t>>4)*2 + (d>>1), i6 = d&1
    {
        const int wb = ((t >> 4) << 1);
        const int lo = (t & 15) << 2;
#pragma unroll
        for (int d = 0; d < 4; ++d)
            *(float4*)&s[(wb + (d >> 1)) * 136 + (d & 1) * 68 + lo] = u[d];
    }
    __syncthreads();

    // ---- Phase 2: regs own q = i[5:2]; in-place (verified conflict-free) ---
    const int base2 = (t >> 3) * 136 + ((t >> 2) & 1) * 68 + (t & 3);
    float v[16];
#pragma unroll
    for (int q = 0; q < 16; ++q) v[q] = s[base2 + (q << 2)];

#pragma unroll
    for (int m = 1; m <= 8; m <<= 1) {
#pragma unroll
        for (int q = 0; q < 16; ++q) {
            if (!(q & m)) {
                float a = v[q], b = v[q | m];
                v[q]     = a + b;
                v[q | m] = a - b;
            }
        }
    }
#pragma unroll
    for (int q = 0; q < 16; ++q) s[base2 + (q << 2)] = v[q];
    __syncthreads();

    // ---- Phase 3: regs own r = i[10:7]; thread = i[6:0] = t -----------------
    const int wb3 = ((t >> 6) * 68) + (t & 63);
#pragma unroll
    for (int r = 0; r < 16; ++r) v[r] = s[r * 136 + wb3];

    // butterflies on bits 7..10 (r index)
#pragma unroll
    for (int m = 1; m <= 8; m <<= 1) {
#pragma unroll
        for (int r = 0; r < 16; ++r) {
            if (!(r & m)) {
                float a = v[r], b = v[r | m];
                v[r]     = a + b;
                v[r | m] = a - b;
            }
        }
    }

    // ---- Square, scale, coalesced scalar STG (1 line/warp/instr) ----------
    const float sc = 1.0f / 2048.0f;
    float* o = out + (size_t)row * 2048 + t;
#pragma unroll
    for (int r = 0; r < 16; ++r)
        o[r << 7] = v[r] * v[r] * sc;
}

extern "C" void kernel_launch(void* const* d_in, const int* in_sizes, int n_in,
                              void* d_out, int out_size)
{
    const float* x1 = (const float*)d_in[0];   // (8192, 1024) f32
    const float* x2 = (const float*)d_in[1];   // (8192, 1024) f32
    float* out = (float*)d_out;                // (8192, 2048) f32

    const int rows = in_sizes[0] / 1024;       // 8192
    qfl_wht_kernel<<<rows, 128>>>(x1, x2, out);
}